// round 16
// baseline (speedup 1.0000x reference)
#include <cuda_runtime.h>
#include <cuda_fp16.h>
#include <cstdint>

__device__ __forceinline__ uint32_t smem_u32(const void* p) {
    uint32_t a;
    asm("{ .reg .u64 t; cvta.to.shared.u64 t, %1; cvt.u32.u64 %0, t; }" : "=r"(a) : "l"(p));
    return a;
}

// ============================ weight prep =====================================
// g_W3[chunk][tap][oc][psi] : half2 = (W[ic0+2p], W[ic0+2p+1]), psi(p)=(p&3)*2+(p>>2)
// LDG.64 at u32 offset 2*tig yields pairs {tig, tig+4} = (b0, b1) of m16n8k16.
__device__ uint32_t g_W3[4 * 9 * 64 * 8];

__global__ void prep_weights(const float* __restrict__ Wt) {
    int i = blockIdx.x * 256 + threadIdx.x;   // 18432 total
    if (i >= 4 * 9 * 64 * 8) return;
    int q     = i & 7;
    int oc    = (i >> 3) & 63;
    int tap   = (i >> 9) % 9;
    int chunk = i / (512 * 9);
    int p     = (q >> 1) + (q & 1) * 4;       // inverse psi
    int kh    = tap / 3;
    int kw    = tap % 3;
    int ic    = chunk * 16 + 2 * p;
    float w0 = Wt[((oc * 64 + ic) * 3 + kh) * 3 + kw];
    float w1 = Wt[((oc * 64 + ic + 1) * 3 + kh) * 3 + kw];
    __half2 hv = __floats2half2_rn(w0, w1);
    g_W3[i] = *(uint32_t*)&hv;
}

// CTA: 5 output rows x 64 px x 64 oc, 320 threads (10 warps), 2 CTAs/SM.
// SMEM (u32): sIn[2 buf][7 r][2 ph][66 col][4] = 2*3696, bias 64  (~30 KB)
#define THREADS 320
#define ROWS_OUT 5
#define SROWS 7
#define COLS 66
#define SIN_BUF (SROWS * 2 * COLS * 4)           // 3696 u32 per buffer
#define SMEM_BYTES ((2 * SIN_BUF + 64) * 4)

__global__ __launch_bounds__(THREADS, 2)
void conv_f16_mma_kernel(const float* __restrict__ x,
                         const float* __restrict__ bias,
                         float* __restrict__ out)
{
    extern __shared__ uint32_t sm[];
    uint32_t* sIn = sm;                           // [buf][r][ph][col][4]
    float*    sB  = (float*)(sm + 2 * SIN_BUF);
    const uint32_t sInAddr = smem_u32(sIn);

    const int tid  = threadIdx.x;
    const int lane = tid & 31;
    const int wid  = tid >> 5;                    // 10 warps
    const int g    = lane >> 2;
    const int tig  = lane & 3;
    const int w0   = blockIdx.x * 64;
    const int h0   = blockIdx.y * ROWS_OUT;
    const int n    = blockIdx.z;

    // 10 warps: r_out(5) x oc-half(2); each warp 64 px (1 row) x 32 oc
    const int r_out = wid >> 1;
    const int oc0   = 32 * (wid & 1);

    // ldmatrix per-lane address pieces: matrix row + k-half select
    const int m_lane = (lane & 7) + 8 * ((lane >> 3) & 1);
    const int ph_l   = lane >> 4;
    const uint32_t laneOff = (uint32_t)(ph_l * COLS + m_lane) * 16u;

    if (tid < 64) sB[tid] = bias[tid];

    float c[4][4][4];
    #pragma unroll
    for (int mt = 0; mt < 4; ++mt)
        #pragma unroll
        for (int nt = 0; nt < 4; ++nt)
            #pragma unroll
            for (int r = 0; r < 4; ++r) c[mt][nt][r] = 0.0f;

    // ---- staging: 14 (r,ph) x 66 cols; one uint4 (8 k-halves) per iter ----
    auto stage = [&](int chunk, uint32_t* dst) {
        for (int i = tid; i < SROWS * 2 * COLS; i += THREADS) {
            int col = i % COLS;                    // coalesced across lanes
            int t2  = i / COLS;                    // r*2 + ph
            int r   = t2 >> 1;
            int ph  = t2 & 1;
            int gh  = h0 - 1 + r;
            int gw  = w0 - 1 + col;
            uint4 v = make_uint4(0u, 0u, 0u, 0u);
            if ((unsigned)gh < 256u && (unsigned)gw < 256u) {
                const int icb = chunk * 16 + ph * 8;
                const float* base = x + (((size_t)n * 64 + icb) * 256 + gh) * 256 + gw;
                const int S = 256 * 256;
                __half2 h0v = __floats2half2_rn(__ldg(base),         __ldg(base + S));
                __half2 h1v = __floats2half2_rn(__ldg(base + 2 * S), __ldg(base + 3 * S));
                __half2 h2v = __floats2half2_rn(__ldg(base + 4 * S), __ldg(base + 5 * S));
                __half2 h3v = __floats2half2_rn(__ldg(base + 6 * S), __ldg(base + 7 * S));
                v.x = *(uint32_t*)&h0v;
                v.y = *(uint32_t*)&h1v;
                v.z = *(uint32_t*)&h2v;
                v.w = *(uint32_t*)&h3v;
            }
            *(uint4*)(dst + (size_t)i * 4) = v;    // STS.128, conflict-free
        }
    };

    stage(0, sIn);
    __syncthreads();

    for (int chunk = 0; chunk < 4; ++chunk) {
        const uint32_t bufAddr = sInAddr + (uint32_t)((chunk & 1) * SIN_BUF) * 4u;
        const uint32_t* wC = g_W3 + chunk * (9 * 64 * 8);

        // stage next chunk first: LDGs may drift into the mma window
        if (chunk < 3) stage(chunk + 1, sIn + ((chunk + 1) & 1) * SIN_BUF);

        // ---- compute: 9 taps; A via ldmatrix.x4, B via LDG.64 (L1-hit) ----
        #pragma unroll
        for (int kh = 0; kh < 3; ++kh) {
            const uint32_t rowAddr = bufAddr
                + (uint32_t)((r_out + kh) * 2 * COLS) * 16u + laneOff;
            #pragma unroll
            for (int kw = 0; kw < 3; ++kw) {
                const uint32_t* wB = wC + (kh * 3 + kw) * (64 * 8);
                uint32_t b[4][2];
                #pragma unroll
                for (int nt = 0; nt < 4; ++nt) {
                    const uint2 bv = __ldg((const uint2*)(wB + (oc0 + nt * 8 + g) * 8 + 2 * tig));
                    b[nt][0] = bv.x;
                    b[nt][1] = bv.y;
                }
                const uint32_t aCol = rowAddr + (uint32_t)(kw * 16);
                #pragma unroll
                for (int mt = 0; mt < 4; ++mt) {
                    uint32_t a0, a1, a2, a3;
                    asm volatile(
                        "ldmatrix.sync.aligned.m8n8.x4.shared.b16 {%0,%1,%2,%3}, [%4];"
                        : "=r"(a0), "=r"(a1), "=r"(a2), "=r"(a3)
                        : "r"(aCol + (uint32_t)(mt * 16 * 16)));
                    #pragma unroll
                    for (int nt = 0; nt < 4; ++nt)
                        asm(
                            "mma.sync.aligned.m16n8k16.row.col.f32.f16.f16.f32 "
                            "{%0,%1,%2,%3}, {%4,%5,%6,%7}, {%8,%9}, {%0,%1,%2,%3};"
                            : "+f"(c[mt][nt][0]), "+f"(c[mt][nt][1]),
                              "+f"(c[mt][nt][2]), "+f"(c[mt][nt][3])
                            : "r"(a0), "r"(a1), "r"(a2), "r"(a3),
                              "r"(b[nt][0]), "r"(b[nt][1]));
                }
            }
        }

        __syncthreads();
    }

    // ---- epilogue: bias + store (skip rows past the image for tail tiles) ----
    const int h = h0 + r_out;
    if (h < 256) {
        #pragma unroll
        for (int mt = 0; mt < 4; ++mt) {
            const int px = w0 + mt * 16 + g;
            #pragma unroll
            for (int nt = 0; nt < 4; ++nt) {
                const int oc = oc0 + nt * 8 + 2 * tig;
                const size_t b0 = (((size_t)n * 64 + oc) * 256 + h) * 256;
                const size_t b1 = (((size_t)n * 64 + oc + 1) * 256 + h) * 256;
                out[b0 + px]     = c[mt][nt][0] + sB[oc];
                out[b1 + px]     = c[mt][nt][1] + sB[oc + 1];
                out[b0 + px + 8] = c[mt][nt][2] + sB[oc];
                out[b1 + px + 8] = c[mt][nt][3] + sB[oc + 1];
            }
        }
    }
}

extern "C" void kernel_launch(void* const* d_in, const int* in_sizes, int n_in,
                              void* d_out, int out_size)
{
    const float* x  = (const float*)d_in[0];
    const float* Wt = (const float*)d_in[1];
    const float* b  = (const float*)d_in[2];
    float* out = (float*)d_out;

    cudaFuncSetAttribute(conv_f16_mma_kernel,
                         cudaFuncAttributeMaxDynamicSharedMemorySize, SMEM_BYTES);

    prep_weights<<<72, 256>>>(Wt);

    // (w-quarter, h-tile of 5 rows (52 tiles, last has 1 useful row), n)
    dim3 grid(4, (256 + ROWS_OUT - 1) / ROWS_OUT, 16);
    conv_f16_mma_kernel<<<grid, THREADS, SMEM_BYTES>>>(x, b, out);
}

// round 17
// speedup vs baseline: 1.4262x; 1.4262x over previous
#include <cuda_runtime.h>
#include <cuda_fp16.h>
#include <cstdint>

__device__ __forceinline__ uint32_t smem_u32(const void* p) {
    uint32_t a;
    asm("{ .reg .u64 t; cvta.to.shared.u64 t, %1; cvt.u32.u64 %0, t; }" : "=r"(a) : "l"(p));
    return a;
}

// ============================ weight prep =====================================
// g_W3[chunk][tap][oc][psi] : half2 = (W[ic0+2p], W[ic0+2p+1]), psi(p)=(p&3)*2+(p>>2)
// LDG.64 at u32 offset 2*tig yields pairs {tig, tig+4} = (b0, b1) of m16n8k16.
__device__ uint32_t g_W3[4 * 9 * 64 * 8];

__global__ void prep_weights(const float* __restrict__ Wt) {
    int i = blockIdx.x * 256 + threadIdx.x;   // 18432 total
    if (i >= 4 * 9 * 64 * 8) return;
    int q     = i & 7;
    int oc    = (i >> 3) & 63;
    int tap   = (i >> 9) % 9;
    int chunk = i / (512 * 9);
    int p     = (q >> 1) + (q & 1) * 4;       // inverse psi
    int kh    = tap / 3;
    int kw    = tap % 3;
    int ic    = chunk * 16 + 2 * p;
    float w0 = Wt[((oc * 64 + ic) * 3 + kh) * 3 + kw];
    float w1 = Wt[((oc * 64 + ic + 1) * 3 + kh) * 3 + kw];
    __half2 hv = __floats2half2_rn(w0, w1);
    g_W3[i] = *(uint32_t*)&hv;
}

// CTA: 2 output rows x 64 px x 64 oc, 128 threads (4 warps), 5 CTAs/SM.
// SMEM (u32): sIn[2 buf][4 r][2 ph][66 col][4] = 2*2112, bias 64  (~17 KB)
#define THREADS 128
#define COLS 66
#define SIN_BUF (4 * 2 * COLS * 4)               // 2112 u32 per buffer
#define SMEM_BYTES ((2 * SIN_BUF + 64) * 4)

__global__ __launch_bounds__(THREADS, 5)
void conv_f16_mma_kernel(const float* __restrict__ x,
                         const float* __restrict__ bias,
                         float* __restrict__ out)
{
    extern __shared__ uint32_t sm[];
    uint32_t* sIn = sm;                           // [buf][r][ph][col][4]
    float*    sB  = (float*)(sm + 2 * SIN_BUF);
    const uint32_t sInAddr = smem_u32(sIn);

    const int tid  = threadIdx.x;
    const int lane = tid & 31;
    const int wid  = tid >> 5;                    // 4 warps, 1 per SMSP
    const int g    = lane >> 2;
    const int tig  = lane & 3;
    const int w0   = blockIdx.x * 64;
    const int h0   = blockIdx.y * 2;              // 2 output rows per CTA
    const int n    = blockIdx.z;

    // 4 warps: r_out(2) x oc-half(2); each warp 64 px (1 row) x 32 oc
    const int r_out = wid >> 1;
    const int oc0   = 32 * (wid & 1);

    // ldmatrix per-lane address pieces: matrix row + k-half select
    const int m_lane = (lane & 7) + 8 * ((lane >> 3) & 1);
    const int ph_l   = lane >> 4;
    const uint32_t laneOff = (uint32_t)(ph_l * COLS + m_lane) * 16u;

    if (tid < 64) sB[tid] = bias[tid];

    float c[4][4][4];
    #pragma unroll
    for (int mt = 0; mt < 4; ++mt)
        #pragma unroll
        for (int nt = 0; nt < 4; ++nt)
            #pragma unroll
            for (int r = 0; r < 4; ++r) c[mt][nt][r] = 0.0f;

    // ---- staging: 8 (r,ph) x 66 cols; one uint4 (8 k-halves) per iter ----
    auto stage = [&](int chunk, uint32_t* dst) {
        for (int i = tid; i < 8 * COLS; i += THREADS) {
            int col = i % COLS;                    // coalesced across lanes
            int t2  = i / COLS;                    // r*2 + ph
            int r   = t2 >> 1;
            int ph  = t2 & 1;
            int gh  = h0 - 1 + r;
            int gw  = w0 - 1 + col;
            uint4 v = make_uint4(0u, 0u, 0u, 0u);
            if ((unsigned)gh < 256u && (unsigned)gw < 256u) {
                const int icb = chunk * 16 + ph * 8;
                const float* base = x + (((size_t)n * 64 + icb) * 256 + gh) * 256 + gw;
                const int S = 256 * 256;
                __half2 h0v = __floats2half2_rn(__ldg(base),         __ldg(base + S));
                __half2 h1v = __floats2half2_rn(__ldg(base + 2 * S), __ldg(base + 3 * S));
                __half2 h2v = __floats2half2_rn(__ldg(base + 4 * S), __ldg(base + 5 * S));
                __half2 h3v = __floats2half2_rn(__ldg(base + 6 * S), __ldg(base + 7 * S));
                v.x = *(uint32_t*)&h0v;
                v.y = *(uint32_t*)&h1v;
                v.z = *(uint32_t*)&h2v;
                v.w = *(uint32_t*)&h3v;
            }
            *(uint4*)(dst + (size_t)i * 4) = v;    // STS.128, conflict-free
        }
    };

    stage(0, sIn);
    __syncthreads();

    for (int chunk = 0; chunk < 4; ++chunk) {
        const uint32_t bufAddr = sInAddr + (uint32_t)((chunk & 1) * SIN_BUF) * 4u;
        const uint32_t* wC = g_W3 + chunk * (9 * 64 * 8);

        // stage next chunk first: LDGs may drift into the mma window
        if (chunk < 3) stage(chunk + 1, sIn + ((chunk + 1) & 1) * SIN_BUF);

        // ---- compute: 9 taps; A via ldmatrix.x4, B via LDG.64 (L1-hit) ----
        #pragma unroll
        for (int kh = 0; kh < 3; ++kh) {
            const uint32_t rowAddr = bufAddr
                + (uint32_t)((r_out + kh) * 2 * COLS) * 16u + laneOff;
            #pragma unroll
            for (int kw = 0; kw < 3; ++kw) {
                const uint32_t* wB = wC + (kh * 3 + kw) * (64 * 8);
                uint32_t b[4][2];
                #pragma unroll
                for (int nt = 0; nt < 4; ++nt) {
                    const uint2 bv = __ldg((const uint2*)(wB + (oc0 + nt * 8 + g) * 8 + 2 * tig));
                    b[nt][0] = bv.x;
                    b[nt][1] = bv.y;
                }
                const uint32_t aCol = rowAddr + (uint32_t)(kw * 16);
                #pragma unroll
                for (int mt = 0; mt < 4; ++mt) {
                    uint32_t a0, a1, a2, a3;
                    asm volatile(
                        "ldmatrix.sync.aligned.m8n8.x4.shared.b16 {%0,%1,%2,%3}, [%4];"
                        : "=r"(a0), "=r"(a1), "=r"(a2), "=r"(a3)
                        : "r"(aCol + (uint32_t)(mt * 16 * 16)));
                    #pragma unroll
                    for (int nt = 0; nt < 4; ++nt)
                        asm(
                            "mma.sync.aligned.m16n8k16.row.col.f32.f16.f16.f32 "
                            "{%0,%1,%2,%3}, {%4,%5,%6,%7}, {%8,%9}, {%0,%1,%2,%3};"
                            : "+f"(c[mt][nt][0]), "+f"(c[mt][nt][1]),
                              "+f"(c[mt][nt][2]), "+f"(c[mt][nt][3])
                            : "r"(a0), "r"(a1), "r"(a2), "r"(a3),
                              "r"(b[nt][0]), "r"(b[nt][1]));
                }
            }
        }

        __syncthreads();
    }

    // ---- epilogue: bias + store ----
    const int h = h0 + r_out;
    #pragma unroll
    for (int mt = 0; mt < 4; ++mt) {
        const int px = w0 + mt * 16 + g;
        #pragma unroll
        for (int nt = 0; nt < 4; ++nt) {
            const int oc = oc0 + nt * 8 + 2 * tig;
            const size_t b0 = (((size_t)n * 64 + oc) * 256 + h) * 256;
            const size_t b1 = (((size_t)n * 64 + oc + 1) * 256 + h) * 256;
            out[b0 + px]     = c[mt][nt][0] + sB[oc];
            out[b1 + px]     = c[mt][nt][1] + sB[oc + 1];
            out[b0 + px + 8] = c[mt][nt][2] + sB[oc];
            out[b1 + px + 8] = c[mt][nt][3] + sB[oc + 1];
        }
    }
}

extern "C" void kernel_launch(void* const* d_in, const int* in_sizes, int n_in,
                              void* d_out, int out_size)
{
    const float* x  = (const float*)d_in[0];
    const float* Wt = (const float*)d_in[1];
    const float* b  = (const float*)d_in[2];
    float* out = (float*)d_out;

    cudaFuncSetAttribute(conv_f16_mma_kernel,
                         cudaFuncAttributeMaxDynamicSharedMemorySize, SMEM_BYTES);

    prep_weights<<<72, 256>>>(Wt);

    dim3 grid(4, 128, 16);   // (w-quarter, h-pair, n): 8192 CTAs, 2x64 px x 64 oc
    conv_f16_mma_kernel<<<grid, THREADS, SMEM_BYTES>>>(x, b, out);
}